// round 2
// baseline (speedup 1.0000x reference)
#include <cuda_runtime.h>
#include <math_constants.h>

// ---------------------------------------------------------------------------
// Problem constants
// ---------------------------------------------------------------------------
#define B_  4
#define T_  2048
#define D_  1024
#define H_  16
#define HS_ 64
#define ROWS (B_ * T_)      // 8192
#define DFF (4 * D_)        // 4096

// ---------------------------------------------------------------------------
// Scratch (no allocations allowed -> __device__ globals)
// ---------------------------------------------------------------------------
__device__ float g_xn  [ROWS * D_];        // LN output (reused for LN1 and LN2)
__device__ float g_qkv [ROWS * 3 * D_];    // [row][3072]: q | k | v, head-major cols
__device__ float g_ctx [ROWS * D_];        // attention context, [row][h*64+k]
__device__ float g_x1  [ROWS * D_];        // x + attn-proj (residual stream)
__device__ float g_h   [ROWS * DFF];       // FFN hidden
__device__ float g_wqkv[D_ * 3 * D_];      // packed QKV weight [d][3072]

// ---------------------------------------------------------------------------
// Pack wq/wk/wv [H,D,HS] -> Wqkv [D, 3*D] with col = (which*1024 + h*64 + k)
// ---------------------------------------------------------------------------
__global__ void pack_qkv_kernel(const float* __restrict__ wq,
                                const float* __restrict__ wk,
                                const float* __restrict__ wv,
                                float* __restrict__ W) {
    int idx = blockIdx.x * 256 + threadIdx.x;   // over H*D*HS = 1M
    if (idx >= H_ * D_ * HS_) return;
    int k = idx & (HS_ - 1);
    int d = (idx >> 6) & (D_ - 1);
    int h = idx >> 16;
    int colbase = h * HS_ + k;
    size_t o = (size_t)d * (3 * D_) + colbase;
    W[o]            = wq[idx];
    W[o + D_]       = wk[idx];
    W[o + 2 * D_]   = wv[idx];
}

// ---------------------------------------------------------------------------
// LayerNorm: one block per row of 1024, 256 threads, float4 per thread
// ---------------------------------------------------------------------------
__global__ void __launch_bounds__(256) ln_kernel(const float* __restrict__ x,
                                                 const float* __restrict__ g,
                                                 const float* __restrict__ b,
                                                 float* __restrict__ y) {
    __shared__ float red[8];
    __shared__ float s_mu, s_inv;
    int row = blockIdx.x;
    int tid = threadIdx.x;
    int lane = tid & 31, wid = tid >> 5;

    const float4* xr = (const float4*)(x + (size_t)row * D_);
    float4 v = xr[tid];

    // mean
    float s = v.x + v.y + v.z + v.w;
    #pragma unroll
    for (int off = 16; off >= 1; off >>= 1) s += __shfl_xor_sync(0xffffffffu, s, off);
    if (lane == 0) red[wid] = s;
    __syncthreads();
    if (tid == 0) {
        float t = 0.f;
        #pragma unroll
        for (int i = 0; i < 8; i++) t += red[i];
        s_mu = t * (1.0f / D_);
    }
    __syncthreads();
    float mu = s_mu;

    // variance
    float dx0 = v.x - mu, dx1 = v.y - mu, dx2 = v.z - mu, dx3 = v.w - mu;
    float q = dx0*dx0 + dx1*dx1 + dx2*dx2 + dx3*dx3;
    #pragma unroll
    for (int off = 16; off >= 1; off >>= 1) q += __shfl_xor_sync(0xffffffffu, q, off);
    if (lane == 0) red[wid] = q;
    __syncthreads();
    if (tid == 0) {
        float t = 0.f;
        #pragma unroll
        for (int i = 0; i < 8; i++) t += red[i];
        s_inv = rsqrtf(t * (1.0f / D_) + 1e-5f);
    }
    __syncthreads();
    float inv = s_inv;

    float4 gv = ((const float4*)g)[tid];
    float4 bv = ((const float4*)b)[tid];
    float4 o;
    o.x = dx0 * inv * gv.x + bv.x;
    o.y = dx1 * inv * gv.y + bv.y;
    o.z = dx2 * inv * gv.z + bv.z;
    o.w = dx3 * inv * gv.w + bv.w;
    ((float4*)(y + (size_t)row * D_))[tid] = o;
}

// ---------------------------------------------------------------------------
// SGEMM: C[M,N] = A[M,K] @ B[K,N]  (+bias) (+resid) (relu)
// 128x128 block tile, BK=8, 256 threads, 8x8 per thread.
// All of M,N,K are multiples of 128 here -> no bounds checks.
// ---------------------------------------------------------------------------
template<bool RELU, bool HAS_BIAS, bool HAS_RES>
__global__ void __launch_bounds__(256) sgemm_kernel(
    int M, int N, int K,
    const float* __restrict__ A, const float* __restrict__ Bm,
    const float* __restrict__ bias, const float* __restrict__ resid,
    float* __restrict__ C) {
    __shared__ float As[8][128];
    __shared__ float Bs[8][128];

    int tid = threadIdx.x;
    int mbase = blockIdx.y * 128;
    int nbase = blockIdx.x * 128;
    int ty = tid >> 4, tx = tid & 15;

    float acc[8][8];
    #pragma unroll
    for (int i = 0; i < 8; i++)
        #pragma unroll
        for (int j = 0; j < 8; j++) acc[i][j] = 0.f;

    int arow = tid >> 1;                // 0..127
    int acol = (tid & 1) << 2;          // 0 or 4
    int brow = tid >> 5;                // 0..7
    int bcol = (tid & 31) << 2;         // 0..124

    const float* Aptr = A + (size_t)(mbase + arow) * K + acol;
    const float* Bptr = Bm + (size_t)brow * N + nbase + bcol;

    for (int k0 = 0; k0 < K; k0 += 8) {
        float4 a4 = *(const float4*)(Aptr + k0);
        float4 b4 = *(const float4*)(Bptr + (size_t)k0 * N);
        As[acol + 0][arow] = a4.x;
        As[acol + 1][arow] = a4.y;
        As[acol + 2][arow] = a4.z;
        As[acol + 3][arow] = a4.w;
        *(float4*)&Bs[brow][bcol] = b4;
        __syncthreads();

        #pragma unroll
        for (int k = 0; k < 8; k++) {
            float ar[8], br[8];
            *(float4*)(ar)     = *(const float4*)&As[k][ty * 8];
            *(float4*)(ar + 4) = *(const float4*)&As[k][ty * 8 + 4];
            *(float4*)(br)     = *(const float4*)&Bs[k][tx * 8];
            *(float4*)(br + 4) = *(const float4*)&Bs[k][tx * 8 + 4];
            #pragma unroll
            for (int i = 0; i < 8; i++)
                #pragma unroll
                for (int j = 0; j < 8; j++)
                    acc[i][j] += ar[i] * br[j];
        }
        __syncthreads();
    }

    #pragma unroll
    for (int i = 0; i < 8; i++) {
        int row = mbase + ty * 8 + i;
        size_t roff = (size_t)row * N + nbase + tx * 8;
        float out[8];
        #pragma unroll
        for (int j = 0; j < 8; j++) {
            float v = acc[i][j];
            if (HAS_BIAS) v += bias[nbase + tx * 8 + j];
            if (HAS_RES)  v += resid[roff + j];
            if (RELU)     v = fmaxf(v, 0.f);
            out[j] = v;
        }
        *(float4*)(C + roff)     = make_float4(out[0], out[1], out[2], out[3]);
        *(float4*)(C + roff + 4) = make_float4(out[4], out[5], out[6], out[7]);
    }
}

// ---------------------------------------------------------------------------
// Flash attention (fp32, causal). Grid: (T/64, B*H). 256 threads.
// Thread grid 16x16, each thread owns a 4x4 micro-tile of the 64x64 S tile.
// Shared (dynamic): Qs[64][68], Kt[64][68] (k-major), Vs[64][68], Ps[64][68].
// Row-stride 68 floats = 272 B (16B-aligned, odd*16 -> conflict-free float4).
// ---------------------------------------------------------------------------
#define SPITCH 68

__global__ void __launch_bounds__(256) attn_kernel(const float* __restrict__ qkv,
                                                   float* __restrict__ ctx) {
    extern __shared__ float sm[];
    float* Qs = sm;
    float* Kt = Qs + 64 * SPITCH;
    float* Vs = Kt + 64 * SPITCH;
    float* Ps = Vs + 64 * SPITCH;

    int qtile = blockIdx.x;           // 0..31
    int bh = blockIdx.y;              // 0..63
    int b = bh >> 4, h = bh & 15;
    int tid = threadIdx.x;
    int ty = tid >> 4, tx = tid & 15;
    int r0 = ty * 4, c0 = tx * 4;
    const float scale = 0.125f;       // HS^-0.5

    size_t rowbase = (size_t)(b * T_ + qtile * 64) * (3 * D_) + h * HS_;

    // Load Q tile (pre-scaled)
    for (int it = tid; it < 64 * 16; it += 256) {
        int r = it >> 4, c4 = (it & 15) << 2;
        float4 v = *(const float4*)(qkv + rowbase + (size_t)r * (3 * D_) + c4);
        v.x *= scale; v.y *= scale; v.z *= scale; v.w *= scale;
        *(float4*)&Qs[r * SPITCH + c4] = v;
    }

    float m_old[4], lsum[4], o[4][4];
    #pragma unroll
    for (int i = 0; i < 4; i++) {
        m_old[i] = -CUDART_INF_F;
        lsum[i] = 0.f;
        #pragma unroll
        for (int c = 0; c < 4; c++) o[i][c] = 0.f;
    }

    for (int jt = 0; jt <= qtile; jt++) {
        __syncthreads();   // protect Kt/Vs/Ps from previous iteration readers

        // Load K (transposed into Kt) and V
        size_t kbase = (size_t)(b * T_ + jt * 64) * (3 * D_) + D_ + h * HS_;
        for (int it = tid; it < 64 * 16; it += 256) {
            int s = it >> 4, c4 = (it & 15) << 2;
            size_t base = kbase + (size_t)s * (3 * D_) + c4;   // FIXED: + c4
            float4 kv = *(const float4*)(qkv + base);
            float4 vv = *(const float4*)(qkv + base + D_);
            Kt[(c4 + 0) * SPITCH + s] = kv.x;
            Kt[(c4 + 1) * SPITCH + s] = kv.y;
            Kt[(c4 + 2) * SPITCH + s] = kv.z;
            Kt[(c4 + 3) * SPITCH + s] = kv.w;
            *(float4*)&Vs[s * SPITCH + c4] = vv;
        }
        __syncthreads();

        // S = Q K^T (scaled)
        float sacc[4][4];
        #pragma unroll
        for (int i = 0; i < 4; i++)
            #pragma unroll
            for (int j = 0; j < 4; j++) sacc[i][j] = 0.f;

        #pragma unroll 8
        for (int kk = 0; kk < 64; kk++) {
            float4 kv = *(const float4*)&Kt[kk * SPITCH + c0];
            float q0 = Qs[(r0 + 0) * SPITCH + kk];
            float q1 = Qs[(r0 + 1) * SPITCH + kk];
            float q2 = Qs[(r0 + 2) * SPITCH + kk];
            float q3 = Qs[(r0 + 3) * SPITCH + kk];
            sacc[0][0] += q0 * kv.x; sacc[0][1] += q0 * kv.y; sacc[0][2] += q0 * kv.z; sacc[0][3] += q0 * kv.w;
            sacc[1][0] += q1 * kv.x; sacc[1][1] += q1 * kv.y; sacc[1][2] += q1 * kv.z; sacc[1][3] += q1 * kv.w;
            sacc[2][0] += q2 * kv.x; sacc[2][1] += q2 * kv.y; sacc[2][2] += q2 * kv.z; sacc[2][3] += q2 * kv.w;
            sacc[3][0] += q3 * kv.x; sacc[3][1] += q3 * kv.y; sacc[3][2] += q3 * kv.z; sacc[3][3] += q3 * kv.w;
        }

        // Causal mask only on diagonal tile: key col (c0+j) > query row (r0+i)
        if (jt == qtile) {
            #pragma unroll
            for (int i = 0; i < 4; i++)
                #pragma unroll
                for (int j = 0; j < 4; j++)
                    if (c0 + j > r0 + i) sacc[i][j] = -CUDART_INF_F;
        }

        // Online softmax per row (row spread across 16 contiguous lanes)
        #pragma unroll
        for (int i = 0; i < 4; i++) {
            float tmax = fmaxf(fmaxf(sacc[i][0], sacc[i][1]), fmaxf(sacc[i][2], sacc[i][3]));
            #pragma unroll
            for (int off = 8; off >= 1; off >>= 1)
                tmax = fmaxf(tmax, __shfl_xor_sync(0xffffffffu, tmax, off));
            float m_new = fmaxf(m_old[i], tmax);

            float p0 = __expf(sacc[i][0] - m_new);
            float p1 = __expf(sacc[i][1] - m_new);
            float p2 = __expf(sacc[i][2] - m_new);
            float p3 = __expf(sacc[i][3] - m_new);
            float rs = p0 + p1 + p2 + p3;
            #pragma unroll
            for (int off = 8; off >= 1; off >>= 1)
                rs += __shfl_xor_sync(0xffffffffu, rs, off);

            float alpha = __expf(m_old[i] - m_new);
            lsum[i] = lsum[i] * alpha + rs;
            #pragma unroll
            for (int c = 0; c < 4; c++) o[i][c] *= alpha;
            m_old[i] = m_new;

            *(float4*)&Ps[(r0 + i) * SPITCH + c0] = make_float4(p0, p1, p2, p3);
        }
        __syncthreads();

        // O += P V
        #pragma unroll 8
        for (int ss = 0; ss < 64; ss++) {
            float4 vv = *(const float4*)&Vs[ss * SPITCH + c0];
            float p0 = Ps[(r0 + 0) * SPITCH + ss];
            float p1 = Ps[(r0 + 1) * SPITCH + ss];
            float p2 = Ps[(r0 + 2) * SPITCH + ss];
            float p3 = Ps[(r0 + 3) * SPITCH + ss];
            o[0][0] += p0 * vv.x; o[0][1] += p0 * vv.y; o[0][2] += p0 * vv.z; o[0][3] += p0 * vv.w;
            o[1][0] += p1 * vv.x; o[1][1] += p1 * vv.y; o[1][2] += p1 * vv.z; o[1][3] += p1 * vv.w;
            o[2][0] += p2 * vv.x; o[2][1] += p2 * vv.y; o[2][2] += p2 * vv.z; o[2][3] += p2 * vv.w;
            o[3][0] += p3 * vv.x; o[3][1] += p3 * vv.y; o[3][2] += p3 * vv.z; o[3][3] += p3 * vv.w;
        }
    }

    // Write ctx[(b*T + q)][h*64 + c]
    #pragma unroll
    for (int i = 0; i < 4; i++) {
        float inv = 1.0f / lsum[i];
        int grow = b * T_ + qtile * 64 + r0 + i;
        float4 out = make_float4(o[i][0] * inv, o[i][1] * inv, o[i][2] * inv, o[i][3] * inv);
        *(float4*)(ctx + (size_t)grow * D_ + h * HS_ + c0) = out;
    }
}

// ---------------------------------------------------------------------------
// Launcher
// ---------------------------------------------------------------------------
extern "C" void kernel_launch(void* const* d_in, const int* in_sizes, int n_in,
                              void* d_out, int out_size) {
    (void)in_sizes; (void)n_in; (void)out_size;
    const float* x      = (const float*)d_in[0];
    const float* ln1_g  = (const float*)d_in[1];
    const float* ln1_b  = (const float*)d_in[2];
    const float* wq     = (const float*)d_in[3];
    const float* wk     = (const float*)d_in[4];
    const float* wv     = (const float*)d_in[5];
    const float* w_proj = (const float*)d_in[6];
    const float* b_proj = (const float*)d_in[7];
    const float* ln2_g  = (const float*)d_in[8];
    const float* ln2_b  = (const float*)d_in[9];
    const float* w1     = (const float*)d_in[10];
    const float* b1     = (const float*)d_in[11];
    const float* w2     = (const float*)d_in[12];
    const float* b2     = (const float*)d_in[13];
    float* out = (float*)d_out;

    float *xn, *qkv, *ctx, *x1, *hbuf, *wqkv;
    cudaGetSymbolAddress((void**)&xn,   g_xn);
    cudaGetSymbolAddress((void**)&qkv,  g_qkv);
    cudaGetSymbolAddress((void**)&ctx,  g_ctx);
    cudaGetSymbolAddress((void**)&x1,   g_x1);
    cudaGetSymbolAddress((void**)&hbuf, g_h);
    cudaGetSymbolAddress((void**)&wqkv, g_wqkv);

    // 1. Pack QKV weights
    pack_qkv_kernel<<<(H_ * D_ * HS_ + 255) / 256, 256>>>(wq, wk, wv, wqkv);

    // 2. LN1
    ln_kernel<<<ROWS, 256>>>(x, ln1_g, ln1_b, xn);

    // 3. QKV GEMM: [8192,1024] @ [1024,3072]
    sgemm_kernel<false, false, false><<<dim3(3 * D_ / 128, ROWS / 128), 256>>>(
        ROWS, 3 * D_, D_, xn, wqkv, nullptr, nullptr, qkv);

    // 4. Flash attention
    static const int ATTN_SMEM = 4 * 64 * SPITCH * (int)sizeof(float);  // 69632
    cudaFuncSetAttribute(attn_kernel, cudaFuncAttributeMaxDynamicSharedMemorySize, ATTN_SMEM);
    attn_kernel<<<dim3(T_ / 64, B_ * H_), 256, ATTN_SMEM>>>(qkv, ctx);

    // 5. Proj + bias + residual: x1 = x + ctx @ w_proj + b_proj
    sgemm_kernel<false, true, true><<<dim3(D_ / 128, ROWS / 128), 256>>>(
        ROWS, D_, D_, ctx, w_proj, b_proj, x, x1);

    // 6. LN2
    ln_kernel<<<ROWS, 256>>>(x1, ln2_g, ln2_b, xn);

    // 7. FFN1 + bias + relu: h = relu(xn @ w1 + b1)
    sgemm_kernel<true, true, false><<<dim3(DFF / 128, ROWS / 128), 256>>>(
        ROWS, DFF, D_, xn, w1, b1, nullptr, hbuf);

    // 8. FFN2 + bias + residual: out = x1 + h @ w2 + b2
    sgemm_kernel<false, true, true><<<dim3(D_ / 128, ROWS / 128), 256>>>(
        ROWS, D_, DFF, hbuf, w2, b2, x1, out);
}

// round 6
// speedup vs baseline: 1.9745x; 1.9745x over previous
#include <cuda_runtime.h>
#include <cuda_bf16.h>
#include <math_constants.h>
#include <cstdint>

// ---------------------------------------------------------------------------
// Problem constants
// ---------------------------------------------------------------------------
#define B_  4
#define T_  2048
#define D_  1024
#define H_  16
#define HS_ 64
#define ROWS (B_ * T_)      // 8192
#define DFF (4 * D_)        // 4096

// ---------------------------------------------------------------------------
// Scratch (no allocations allowed -> __device__ globals)
// ---------------------------------------------------------------------------
__device__ float          g_qkv [ROWS * 3 * D_];          // fp32 q|k|v (attn input)
__device__ float          g_x1  [ROWS * D_];              // residual stream after attn
__device__ __nv_bfloat16  g_xn3 [ROWS * 3 * D_];          // LN out, [hi|lo|hi] packed
__device__ __nv_bfloat16  g_ctx3[ROWS * 3 * D_];          // attn ctx, [hi|lo|hi] packed
__device__ __nv_bfloat16  g_h3  [(size_t)ROWS * 3 * DFF]; // ffn hidden, [hi|lo|hi]
__device__ __nv_bfloat16  g_wqkv3t [3 * D_ * 3 * D_];     // [3072][3072] (N,3K) K-major
__device__ __nv_bfloat16  g_wproj3t[D_ * 3 * D_];         // [1024][3072]
__device__ __nv_bfloat16  g_w13t   [DFF * 3 * D_];        // [4096][3072]
__device__ __nv_bfloat16  g_w23t   [(size_t)D_ * 3 * DFF];// [1024][12288]

// ---------------------------------------------------------------------------
// PTX helpers (baseline sm_100 ISA only: cp.async + ldmatrix + mma.sync)
// ---------------------------------------------------------------------------
__device__ __forceinline__ uint32_t smem_to_u32(const void* p) {
    uint32_t a;
    asm("{ .reg .u64 t; cvta.to.shared.u64 t, %1; cvt.u32.u64 %0, t; }" : "=r"(a) : "l"(p));
    return a;
}

#define CP_ASYNC16(saddr, gptr) \
    asm volatile("cp.async.cg.shared.global [%0], [%1], 16;" :: "r"(saddr), "l"(gptr) : "memory")
#define CP_COMMIT() asm volatile("cp.async.commit_group;" ::: "memory")
#define CP_WAIT0()  asm volatile("cp.async.wait_group 0;" ::: "memory")
#define CP_WAIT1()  asm volatile("cp.async.wait_group 1;" ::: "memory")

#define LDMATRIX_X4(r0, r1, r2, r3, addr) \
    asm volatile("ldmatrix.sync.aligned.m8n8.x4.shared.b16 {%0,%1,%2,%3}, [%4];" \
                 : "=r"(r0), "=r"(r1), "=r"(r2), "=r"(r3) : "r"(addr))

#define MMA16816(d, a, b0, b1) \
    asm volatile("mma.sync.aligned.m16n8k16.row.col.f32.bf16.bf16.f32 " \
                 "{%0,%1,%2,%3}, {%4,%5,%6,%7}, {%8,%9}, {%0,%1,%2,%3};" \
                 : "+f"((d)[0]), "+f"((d)[1]), "+f"((d)[2]), "+f"((d)[3]) \
                 : "r"((a)[0]), "r"((a)[1]), "r"((a)[2]), "r"((a)[3]), \
                   "r"(b0), "r"(b1))

// ---------------------------------------------------------------------------
// bf16 split helpers: x = hi + lo  (each bf16, rn)
// ---------------------------------------------------------------------------
__device__ __forceinline__ uint32_t packbf2(__nv_bfloat16 a, __nv_bfloat16 b) {
    __nv_bfloat162 t; t.x = a; t.y = b;
    return *reinterpret_cast<uint32_t*>(&t);
}
__device__ __forceinline__ void split_pair(float a, float b, uint32_t& hi, uint32_t& lo) {
    __nv_bfloat16 ha = __float2bfloat16(a);
    __nv_bfloat16 hb = __float2bfloat16(b);
    float ra = a - __bfloat162float(ha);
    float rb = b - __bfloat162float(hb);
    hi = packbf2(ha, hb);
    lo = packbf2(__float2bfloat16(ra), __float2bfloat16(rb));
}

// ---------------------------------------------------------------------------
// Weight split kernels: W[K,N] fp32 -> out[N][3K] bf16 K-major, cols [Bh|Bh|Bl]
// ---------------------------------------------------------------------------
__global__ void wsplit_kernel(const float* __restrict__ W, __nv_bfloat16* __restrict__ out,
                              int K, int N) {
    int i = blockIdx.x * 256 + threadIdx.x;
    if (i >= K * N) return;
    int n = i % N, k = i / N;
    float v = W[i];
    __nv_bfloat16 hi = __float2bfloat16(v);
    __nv_bfloat16 lo = __float2bfloat16(v - __bfloat162float(hi));
    size_t ro = (size_t)n * (3 * K);
    out[ro + k] = hi;
    out[ro + K + k] = hi;
    out[ro + 2 * K + k] = lo;
}

// wq/wk/wv [H,D,HS] -> [N=3072][3K=3072], row n = which*1024 + h*64 + hs, col d
__global__ void wqkv_split_kernel(const float* __restrict__ wq, const float* __restrict__ wk,
                                  const float* __restrict__ wv, __nv_bfloat16* __restrict__ out) {
    int i = blockIdx.x * 256 + threadIdx.x;   // over H*D*HS = 1M
    if (i >= H_ * D_ * HS_) return;
    int hs = i & 63, d = (i >> 6) & 1023, h = i >> 16;
    const float* srcs[3] = {wq, wk, wv};
    #pragma unroll
    for (int w = 0; w < 3; w++) {
        float v = srcs[w][i];
        __nv_bfloat16 hi = __float2bfloat16(v);
        __nv_bfloat16 lo = __float2bfloat16(v - __bfloat162float(hi));
        int n = w * 1024 + h * 64 + hs;
        size_t ro = (size_t)n * 3072;
        out[ro + d] = hi;
        out[ro + 1024 + d] = hi;
        out[ro + 2048 + d] = lo;
    }
}

// ---------------------------------------------------------------------------
// LayerNorm -> split-packed bf16 A3 output [row][3072] = [hi|lo|hi]
// ---------------------------------------------------------------------------
__global__ void __launch_bounds__(256) ln_kernel(const float* __restrict__ x,
                                                 const float* __restrict__ g,
                                                 const float* __restrict__ b,
                                                 __nv_bfloat16* __restrict__ y3) {
    __shared__ float red[8];
    __shared__ float s_mu, s_inv;
    int row = blockIdx.x;
    int tid = threadIdx.x;
    int lane = tid & 31, wid = tid >> 5;

    const float4* xr = (const float4*)(x + (size_t)row * D_);
    float4 v = xr[tid];

    float s = v.x + v.y + v.z + v.w;
    #pragma unroll
    for (int off = 16; off >= 1; off >>= 1) s += __shfl_xor_sync(0xffffffffu, s, off);
    if (lane == 0) red[wid] = s;
    __syncthreads();
    if (tid == 0) {
        float t = 0.f;
        #pragma unroll
        for (int i = 0; i < 8; i++) t += red[i];
        s_mu = t * (1.0f / D_);
    }
    __syncthreads();
    float mu = s_mu;

    float dx0 = v.x - mu, dx1 = v.y - mu, dx2 = v.z - mu, dx3 = v.w - mu;
    float q = dx0*dx0 + dx1*dx1 + dx2*dx2 + dx3*dx3;
    #pragma unroll
    for (int off = 16; off >= 1; off >>= 1) q += __shfl_xor_sync(0xffffffffu, q, off);
    if (lane == 0) red[wid] = q;
    __syncthreads();
    if (tid == 0) {
        float t = 0.f;
        #pragma unroll
        for (int i = 0; i < 8; i++) t += red[i];
        s_inv = rsqrtf(t * (1.0f / D_) + 1e-5f);
    }
    __syncthreads();
    float inv = s_inv;

    float4 gv = ((const float4*)g)[tid];
    float4 bv = ((const float4*)b)[tid];
    float4 o;
    o.x = dx0 * inv * gv.x + bv.x;
    o.y = dx1 * inv * gv.y + bv.y;
    o.z = dx2 * inv * gv.z + bv.z;
    o.w = dx3 * inv * gv.w + bv.w;

    uint32_t h01, l01, h23, l23;
    split_pair(o.x, o.y, h01, l01);
    split_pair(o.z, o.w, h23, l23);
    int j = tid * 4;
    size_t rb = (size_t)row * 3072;
    *(uint2*)&y3[rb + j]        = make_uint2(h01, h23);
    *(uint2*)&y3[rb + 1024 + j] = make_uint2(l01, l23);
    *(uint2*)&y3[rb + 2048 + j] = make_uint2(h01, h23);
}

// ---------------------------------------------------------------------------
// bf16 mma.sync GEMM:  C[M,N] = A3[M,K3] @ B3t[N,K3]^T  (both K-major)
// CTA tile 128x128, BK=64 (128B rows, SW128 swizzle), 256 threads (8 warps,
// 2x4 warp grid, warp tile 64x32), double-buffered cp.async.
// Fused epilogue: bias / residual / relu; optional SPLIT3 bf16 [hi|lo|hi] out.
// ---------------------------------------------------------------------------
#define BM 128
#define BN 128
#define BK 64
#define STAGE_BYTES (BM * 128 + BN * 128)   // 32768
#define GEMM_SMEM (2 * STAGE_BYTES)         // 65536

template<bool HAS_BIAS, bool HAS_RES, bool RELU, bool SPLIT3>
__global__ void __launch_bounds__(256, 2) gemm_mma(
    int N, int K3,
    const __nv_bfloat16* __restrict__ A,
    const __nv_bfloat16* __restrict__ Bt,
    const float* __restrict__ bias,
    const float* __restrict__ resid,
    float* __restrict__ Cf,
    __nv_bfloat16* __restrict__ C3,
    int Ksp)
{
    extern __shared__ char smem[];
    const uint32_t su = smem_to_u32(smem);
    int tid = threadIdx.x;
    int lane = tid & 31;
    int w = tid >> 5;
    int wm = (w & 1) * 64;      // warp m-offset in CTA tile
    int wn = (w >> 1) * 32;     // warp n-offset
    int nbase = blockIdx.x * BN;
    int mbase = blockIdx.y * BM;
    const int NK = K3 / BK;

    float acc[4][4][4];
    #pragma unroll
    for (int mi = 0; mi < 4; mi++)
        #pragma unroll
        for (int nj = 0; nj < 4; nj++)
            #pragma unroll
            for (int q = 0; q < 4; q++) acc[mi][nj][q] = 0.f;

    // --- cp.async tile loader (stage = t & 1) -------------------------------
    // SW128 on 128B rows: addr = row*128 + (kb ^ ((row&7)<<4))
    auto load_tile = [&](int t) {
        int s = t & 1;
        uint32_t sA = su + s * STAGE_BYTES;
        uint32_t sB = sA + BM * 128;
        int k0 = t * BK;
        #pragma unroll
        for (int i = 0; i < 4; i++) {
            int ch = tid + i * 256;
            int r = ch >> 3, c = ch & 7;
            const __nv_bfloat16* gp = A + (size_t)(mbase + r) * K3 + k0 + c * 8;
            CP_ASYNC16(sA + r * 128 + ((c * 16) ^ ((r & 7) << 4)), gp);
        }
        #pragma unroll
        for (int i = 0; i < 4; i++) {
            int ch = tid + i * 256;
            int r = ch >> 3, c = ch & 7;
            const __nv_bfloat16* gp = Bt + (size_t)(nbase + r) * K3 + k0 + c * 8;
            CP_ASYNC16(sB + r * 128 + ((c * 16) ^ ((r & 7) << 4)), gp);
        }
        CP_COMMIT();
    };

    // --- ldmatrix address precompute ----------------------------------------
    // A frags (m16k16): lanes 0-15 -> rows 0-15 @k0, lanes 16-31 -> rows @k+8
    int arow = wm + (lane & 15);
    uint32_t a_rowoff = (uint32_t)arow * 128;
    uint32_t a_kmask = (uint32_t)(arow & 7) << 4;
    uint32_t a_kbase = (uint32_t)(lane >> 4) * 16;     // +8 elems = +16B
    // B frags (n16 group, k16): lanes0-7 n0-7@k0, 8-15 n0-7@k8, 16-23 n8-15@k0, 24-31 n8-15@k8
    int brow = wn + (lane & 7) + ((lane >> 4) & 1) * 8;
    uint32_t b_rowoff = (uint32_t)brow * 128;
    uint32_t b_kmask = (uint32_t)(brow & 7) << 4;
    uint32_t b_kbase = (uint32_t)((lane >> 3) & 1) * 16;

    // --- pipelined mainloop -------------------------------------------------
    load_tile(0);
    for (int kt = 0; kt < NK; kt++) {
        if (kt + 1 < NK) { load_tile(kt + 1); CP_WAIT1(); }
        else            { CP_WAIT0(); }
        __syncthreads();

        uint32_t sA = su + (kt & 1) * STAGE_BYTES;
        uint32_t sB = sA + BM * 128;

        #pragma unroll
        for (int ks = 0; ks < 4; ks++) {
            uint32_t a[4][4];
            #pragma unroll
            for (int mi = 0; mi < 4; mi++) {
                uint32_t addr = sA + a_rowoff + mi * (16 * 128)
                              + ((ks * 32 + a_kbase) ^ a_kmask);
                LDMATRIX_X4(a[mi][0], a[mi][1], a[mi][2], a[mi][3], addr);
            }
            uint32_t bf[2][4];
            #pragma unroll
            for (int g = 0; g < 2; g++) {
                uint32_t addr = sB + b_rowoff + g * (16 * 128)
                              + ((ks * 32 + b_kbase) ^ b_kmask);
                LDMATRIX_X4(bf[g][0], bf[g][1], bf[g][2], bf[g][3], addr);
            }
            #pragma unroll
            for (int mi = 0; mi < 4; mi++)
                #pragma unroll
                for (int nj = 0; nj < 4; nj++)
                    MMA16816(acc[mi][nj], a[mi],
                             bf[nj >> 1][(nj & 1) * 2], bf[nj >> 1][(nj & 1) * 2 + 1]);
        }
        __syncthreads();
    }

    // --- epilogue straight from fragments -----------------------------------
    #pragma unroll
    for (int mi = 0; mi < 4; mi++) {
        #pragma unroll
        for (int nj = 0; nj < 4; nj++) {
            int c0 = nbase + wn + nj * 8 + (lane & 3) * 2;
            #pragma unroll
            for (int hh = 0; hh < 2; hh++) {
                int row = mbase + wm + mi * 16 + (lane >> 2) + hh * 8;
                float v0 = acc[mi][nj][hh * 2];
                float v1 = acc[mi][nj][hh * 2 + 1];
                if (HAS_BIAS) {
                    float2 bv = *(const float2*)&bias[c0];
                    v0 += bv.x; v1 += bv.y;
                }
                if (HAS_RES) {
                    float2 rv = *(const float2*)&resid[(size_t)row * N + c0];
                    v0 += rv.x; v1 += rv.y;
                }
                if (RELU) { v0 = fmaxf(v0, 0.f); v1 = fmaxf(v1, 0.f); }
                if (!SPLIT3) {
                    *(float2*)&Cf[(size_t)row * N + c0] = make_float2(v0, v1);
                } else {
                    uint32_t hi, lo;
                    split_pair(v0, v1, hi, lo);
                    size_t base = (size_t)row * (3 * Ksp) + c0;
                    *(uint32_t*)&C3[base]           = hi;
                    *(uint32_t*)&C3[base + Ksp]     = lo;
                    *(uint32_t*)&C3[base + 2 * Ksp] = hi;
                }
            }
        }
    }
}

// ---------------------------------------------------------------------------
// Flash attention (fp32, causal) — writes split-packed ctx3.
// ---------------------------------------------------------------------------
#define SPITCH 68

__global__ void __launch_bounds__(256) attn_kernel(const float* __restrict__ qkv,
                                                   __nv_bfloat16* __restrict__ ctx3) {
    extern __shared__ float sm[];
    float* Qs = sm;
    float* Kt = Qs + 64 * SPITCH;
    float* Vs = Kt + 64 * SPITCH;
    float* Ps = Vs + 64 * SPITCH;

    int qtile = blockIdx.x;
    int bh = blockIdx.y;
    int b = bh >> 4, h = bh & 15;
    int tid = threadIdx.x;
    int ty = tid >> 4, tx = tid & 15;
    int r0 = ty * 4, c0 = tx * 4;
    const float scale = 0.125f;

    size_t rowbase = (size_t)(b * T_ + qtile * 64) * (3 * D_) + h * HS_;

    for (int it = tid; it < 64 * 16; it += 256) {
        int r = it >> 4, c4 = (it & 15) << 2;
        float4 v = *(const float4*)(qkv + rowbase + (size_t)r * (3 * D_) + c4);
        v.x *= scale; v.y *= scale; v.z *= scale; v.w *= scale;
        *(float4*)&Qs[r * SPITCH + c4] = v;
    }

    float m_old[4], lsum[4], o[4][4];
    #pragma unroll
    for (int i = 0; i < 4; i++) {
        m_old[i] = -CUDART_INF_F;
        lsum[i] = 0.f;
        #pragma unroll
        for (int c = 0; c < 4; c++) o[i][c] = 0.f;
    }

    for (int jt = 0; jt <= qtile; jt++) {
        __syncthreads();
        size_t kbase = (size_t)(b * T_ + jt * 64) * (3 * D_) + D_ + h * HS_;
        for (int it = tid; it < 64 * 16; it += 256) {
            int s = it >> 4, c4 = (it & 15) << 2;
            size_t base = kbase + (size_t)s * (3 * D_) + c4;
            float4 kv = *(const float4*)(qkv + base);
            float4 vv = *(const float4*)(qkv + base + D_);
            Kt[(c4 + 0) * SPITCH + s] = kv.x;
            Kt[(c4 + 1) * SPITCH + s] = kv.y;
            Kt[(c4 + 2) * SPITCH + s] = kv.z;
            Kt[(c4 + 3) * SPITCH + s] = kv.w;
            *(float4*)&Vs[s * SPITCH + c4] = vv;
        }
        __syncthreads();

        float sacc[4][4];
        #pragma unroll
        for (int i = 0; i < 4; i++)
            #pragma unroll
            for (int j = 0; j < 4; j++) sacc[i][j] = 0.f;

        #pragma unroll 8
        for (int kk = 0; kk < 64; kk++) {
            float4 kv = *(const float4*)&Kt[kk * SPITCH + c0];
            float q0 = Qs[(r0 + 0) * SPITCH + kk];
            float q1 = Qs[(r0 + 1) * SPITCH + kk];
            float q2 = Qs[(r0 + 2) * SPITCH + kk];
            float q3 = Qs[(r0 + 3) * SPITCH + kk];
            sacc[0][0] += q0 * kv.x; sacc[0][1] += q0 * kv.y; sacc[0][2] += q0 * kv.z; sacc[0][3] += q0 * kv.w;
            sacc[1][0] += q1 * kv.x; sacc[1][1] += q1 * kv.y; sacc[1][2] += q1 * kv.z; sacc[1][3] += q1 * kv.w;
            sacc[2][0] += q2 * kv.x; sacc[2][1] += q2 * kv.y; sacc[2][2] += q2 * kv.z; sacc[2][3] += q2 * kv.w;
            sacc[3][0] += q3 * kv.x; sacc[3][1] += q3 * kv.y; sacc[3][2] += q3 * kv.z; sacc[3][3] += q3 * kv.w;
        }

        if (jt == qtile) {
            #pragma unroll
            for (int i = 0; i < 4; i++)
                #pragma unroll
                for (int j = 0; j < 4; j++)
                    if (c0 + j > r0 + i) sacc[i][j] = -CUDART_INF_F;
        }

        #pragma unroll
        for (int i = 0; i < 4; i++) {
            float tmax = fmaxf(fmaxf(sacc[i][0], sacc[i][1]), fmaxf(sacc[i][2], sacc[i][3]));
            #pragma unroll
            for (int off = 8; off >= 1; off >>= 1)
                tmax = fmaxf(tmax, __shfl_xor_sync(0xffffffffu, tmax, off));
            float m_new = fmaxf(m_old[i], tmax);

            float p0 = __expf(sacc[i][0] - m_new);
            float p1 = __expf(sacc[i][1] - m_new);
            float p2 = __expf(sacc[i][2] - m_new);
            float p3 = __expf(sacc[i][3] - m_new);
            float rs = p0 + p1 + p2 + p3;
            #pragma unroll
            for (int off = 8; off >= 1; off >>= 1)
                rs += __shfl_xor_sync(0xffffffffu, rs, off);

            float alpha = __expf(m_old[i] - m_new);
            lsum[i] = lsum[i] * alpha + rs;
            #pragma unroll
            for (int c = 0; c < 4; c++) o[i][c] *= alpha;
            m_old[i] = m_new;

            *(float4*)&Ps[(r0 + i) * SPITCH + c0] = make_float4(p0, p1, p2, p3);
        }
        __syncthreads();

        #pragma unroll 8
        for (int ss = 0; ss < 64; ss++) {
            float4 vv = *(const float4*)&Vs[ss * SPITCH + c0];
            float p0 = Ps[(r0 + 0) * SPITCH + ss];
            float p1 = Ps[(r0 + 1) * SPITCH + ss];
            float p2 = Ps[(r0 + 2) * SPITCH + ss];
            float p3 = Ps[(r0 + 3) * SPITCH + ss];
            o[0][0] += p0 * vv.x; o[0][1] += p0 * vv.y; o[0][2] += p0 * vv.z; o[0][3] += p0 * vv.w;
            o[1][0] += p1 * vv.x; o[1][1] += p1 * vv.y; o[1][2] += p1 * vv.z; o[1][3] += p1 * vv.w;
            o[2][0] += p2 * vv.x; o[2][1] += p2 * vv.y; o[2][2] += p2 * vv.z; o[2][3] += p2 * vv.w;
            o[3][0] += p3 * vv.x; o[3][1] += p3 * vv.y; o[3][2] += p3 * vv.z; o[3][3] += p3 * vv.w;
        }
    }

    // split-packed ctx3 write: [hi | lo | hi] over K=1024
    int col = h * HS_ + c0;
    #pragma unroll
    for (int i = 0; i < 4; i++) {
        float inv = 1.0f / lsum[i];
        int grow = b * T_ + qtile * 64 + r0 + i;
        float ox = o[i][0] * inv, oy = o[i][1] * inv, oz = o[i][2] * inv, ow = o[i][3] * inv;
        uint32_t h01, l01, h23, l23;
        split_pair(ox, oy, h01, l01);
        split_pair(oz, ow, h23, l23);
        size_t rb = (size_t)grow * 3072;
        *(uint2*)&ctx3[rb + col]        = make_uint2(h01, h23);
        *(uint2*)&ctx3[rb + 1024 + col] = make_uint2(l01, l23);
        *(uint2*)&ctx3[rb + 2048 + col] = make_uint2(h01, h23);
    }
}

// ---------------------------------------------------------------------------
// Launcher
// ---------------------------------------------------------------------------
extern "C" void kernel_launch(void* const* d_in, const int* in_sizes, int n_in,
                              void* d_out, int out_size) {
    (void)in_sizes; (void)n_in; (void)out_size;
    const float* x      = (const float*)d_in[0];
    const float* ln1_g  = (const float*)d_in[1];
    const float* ln1_b  = (const float*)d_in[2];
    const float* wq     = (const float*)d_in[3];
    const float* wk     = (const float*)d_in[4];
    const float* wv     = (const float*)d_in[5];
    const float* w_proj = (const float*)d_in[6];
    const float* b_proj = (const float*)d_in[7];
    const float* ln2_g  = (const float*)d_in[8];
    const float* ln2_b  = (const float*)d_in[9];
    const float* w1     = (const float*)d_in[10];
    const float* b1     = (const float*)d_in[11];
    const float* w2     = (const float*)d_in[12];
    const float* b2     = (const float*)d_in[13];
    float* out = (float*)d_out;

    float *qkv, *x1;
    __nv_bfloat16 *xn3, *ctx3, *h3, *wqkv3t, *wproj3t, *w13t, *w23t;
    cudaGetSymbolAddress((void**)&qkv,     g_qkv);
    cudaGetSymbolAddress((void**)&x1,      g_x1);
    cudaGetSymbolAddress((void**)&xn3,     g_xn3);
    cudaGetSymbolAddress((void**)&ctx3,    g_ctx3);
    cudaGetSymbolAddress((void**)&h3,      g_h3);
    cudaGetSymbolAddress((void**)&wqkv3t,  g_wqkv3t);
    cudaGetSymbolAddress((void**)&wproj3t, g_wproj3t);
    cudaGetSymbolAddress((void**)&w13t,    g_w13t);
    cudaGetSymbolAddress((void**)&w23t,    g_w23t);

    cudaFuncSetAttribute(gemm_mma<false,false,false,false>,
                         cudaFuncAttributeMaxDynamicSharedMemorySize, GEMM_SMEM);
    cudaFuncSetAttribute(gemm_mma<true,true,false,false>,
                         cudaFuncAttributeMaxDynamicSharedMemorySize, GEMM_SMEM);
    cudaFuncSetAttribute(gemm_mma<true,false,true,true>,
                         cudaFuncAttributeMaxDynamicSharedMemorySize, GEMM_SMEM);
    static const int ATTN_SMEM = 4 * 64 * SPITCH * (int)sizeof(float);
    cudaFuncSetAttribute(attn_kernel, cudaFuncAttributeMaxDynamicSharedMemorySize, ATTN_SMEM);

    // 1. weight conversions (split + transpose)
    wqkv_split_kernel<<<(H_ * D_ * HS_ + 255) / 256, 256>>>(wq, wk, wv, wqkv3t);
    wsplit_kernel<<<(D_ * D_ + 255) / 256, 256>>>(w_proj, wproj3t, D_, D_);
    wsplit_kernel<<<(D_ * DFF + 255) / 256, 256>>>(w1, w13t, D_, DFF);
    wsplit_kernel<<<(DFF * D_ + 255) / 256, 256>>>(w2, w23t, DFF, D_);

    // 2. LN1 -> xn3
    ln_kernel<<<ROWS, 256>>>(x, ln1_g, ln1_b, xn3);

    // 3. QKV GEMM: [8192,3072] = xn3 @ wqkv3t^T  (K3=3072) -> fp32 qkv
    gemm_mma<false,false,false,false><<<dim3(3 * D_ / BN, ROWS / BM), 256, GEMM_SMEM>>>(
        3 * D_, 3072, xn3, wqkv3t, nullptr, nullptr, qkv, nullptr, 0);

    // 4. Flash attention -> ctx3 (split-packed)
    attn_kernel<<<dim3(T_ / 64, B_ * H_), 256, ATTN_SMEM>>>(qkv, ctx3);

    // 5. Proj: x1 = x + ctx @ w_proj + b_proj
    gemm_mma<true,true,false,false><<<dim3(D_ / BN, ROWS / BM), 256, GEMM_SMEM>>>(
        D_, 3072, ctx3, wproj3t, b_proj, x, x1, nullptr, 0);

    // 6. LN2 -> xn3
    ln_kernel<<<ROWS, 256>>>(x1, ln2_g, ln2_b, xn3);

    // 7. FFN1: h3 = split3(relu(xn @ w1 + b1))   (Ksp = 4096)
    gemm_mma<true,false,true,true><<<dim3(DFF / BN, ROWS / BM), 256, GEMM_SMEM>>>(
        DFF, 3072, xn3, w13t, b1, nullptr, nullptr, h3, DFF);

    // 8. FFN2: out = x1 + h @ w2 + b2   (K3 = 12288)
    gemm_mma<true,true,false,false><<<dim3(D_ / BN, ROWS / BM), 256, GEMM_SMEM>>>(
        D_, 3 * DFF, h3, w23t, b2, x1, out, nullptr, 0);
}